// round 3
// baseline (speedup 1.0000x reference)
#include <cuda_runtime.h>

// ---------------------------------------------------------------------------
// CliffordPC — Cl(3,0) predictive coding, algebraically collapsed.
//
// gp(x, W) == reshape(x,[B,Din*8]) @ What, with
//   What[(j,a),(i,c)] = sign(a, a^c) * W[i, j, a^c]     (forward)
//   Whatr[(j,a),(i,c)] = sign(a, a^c)*REV[a^c]*W[j, i, a^c]   (reverse+transpose)
//
// Per iteration (exact refactor of the reference):
//   grad1 = clip( [H1|H2] @ K1  -  XR ),  H1' = H1 - a*grad1
//        K1 = [[M1 + I], [-What2]],  M1 = What1 @ What1r,  XR = x @ What1r
//   grad2 = clip( [H1'|H2] @ K2 ),        H2' = H2 - a*grad2
//        K2 = [[-What2r], [M2]],     M2 = What2 @ What2r
// ---------------------------------------------------------------------------

namespace {

constexpr float ALPHA_C = 0.01f;

// scratch (static device globals: allocation-free)
__device__ float g_W1e [1024u * 2048u];   // What1  [1024,2048]
__device__ float g_W1re[2048u * 1024u];   // What1r [2048,1024]
__device__ float g_K1  [1536u * 1024u];   // [[M1+I],[-What2]]
__device__ float g_K2  [1536u * 512u];    // [[-What2r],[M2]]
__device__ float g_XR  [4096u * 1024u];   // x @ What1r
__device__ float g_H1a [4096u * 1024u];
__device__ float g_H1b [4096u * 1024u];
__device__ float g_H2a [4096u * 512u];
__device__ float g_H2b [4096u * 512u];

__device__ __forceinline__ int reorder_sign(int a, int b) {
    int s = 0;
    int aa = a >> 1;
    while (aa) { s += __popc(aa & b); aa >>= 1; }
    return (s & 1) ? -1 : 1;
}

__device__ __forceinline__ unsigned long long pack2(float x, float y) {
    unsigned long long r;
    asm("mov.b64 %0, {%1, %2};" : "=l"(r) : "f"(x), "f"(y));
    return r;
}
__device__ __forceinline__ float2 unpack2(unsigned long long v) {
    float2 f;
    asm("mov.b64 {%0, %1}, %2;" : "=f"(f.x), "=f"(f.y) : "l"(v));
    return f;
}

// Expand W [I,J,8] (fwd) or W [J,I,8] (rev) into out [J*8, I*8], scaled by sgn.
__global__ void expand_kernel(const float* __restrict__ W, int J, int I,
                              float* __restrict__ out, int rev, float sgn)
{
    int total = J * 8 * I * 8;
    int idx = blockIdx.x * blockDim.x + threadIdx.x;
    if (idx >= total) return;
    int ncol = I * 8;
    int col = idx % ncol;
    int row = idx / ncol;
    int a = row & 7, j = row >> 3;
    int c = col & 7, i = col >> 3;
    int e = a ^ c;
    float s = (float)reorder_sign(a, e) * sgn;
    size_t widx;
    if (rev) {
        int k = __popc(e);
        if ((k * (k - 1) / 2) & 1) s = -s;            // reverse sign per blade grade
        widx = (size_t)j * ncol + (size_t)i * 8 + e;  // W[j,i,e], W is [J,I,8]
    } else {
        widx = (size_t)i * (size_t)(J * 8) + (size_t)j * 8 + e; // W[i,j,e], W is [I,J,8]
    }
    out[idx] = s * W[widx];
}

// ---------------------------------------------------------------------------
// 128x128x16 fp32 GEMM with packed f32x2 FMAs, split-A (concat along K),
// fused epilogues.
//   EPI 0: C = acc
//   EPI 1: C = acc + I (identity on global row==col)
//   EPI 2: g = clip(acc - XR); C = Hold - ALPHA*g   (grad1 / H1 update)
//   EPI 3: g = clip(acc);      C = Hold - ALPHA*g   (grad2 / H2 update)
// ---------------------------------------------------------------------------
template <int EPI>
__global__ __launch_bounds__(256)
void gemm128(const float* __restrict__ A0, const float* __restrict__ A1,
             int lda0, int lda1, int ksplit,
             const float* __restrict__ Bm, int ldb,
             float* __restrict__ C, int ldc, int K,
             const float* __restrict__ XRp,
             const float* __restrict__ Hold, int ldh)
{
    __shared__ float As[16][132];
    __shared__ float Ws[16][132];

    const int m0 = blockIdx.y * 128;
    const int n0 = blockIdx.x * 128;
    const int tid = threadIdx.x;
    const int tr = tid >> 4;   // 0..15
    const int tc = tid & 15;   // 0..15

    unsigned long long acc[8][4];
#pragma unroll
    for (int i = 0; i < 8; ++i)
#pragma unroll
        for (int j = 0; j < 4; ++j) acc[i][j] = 0ull;

    for (int kt = 0; kt < K; kt += 16) {
        // ---- A tile: 128 rows x 16 k, from whichever K-segment this tile is in
        const float* Ab;
        int lda, kk;
        if (kt < ksplit) { Ab = A0; lda = lda0; kk = kt; }
        else             { Ab = A1; lda = lda1; kk = kt - ksplit; }
#pragma unroll
        for (int u = 0; u < 2; ++u) {
            int f = tid + u * 256;           // float4 id (0..511)
            int row = f >> 2;                // 0..127
            int kc4 = (f & 3) * 4;           // 0,4,8,12
            float4 v = *reinterpret_cast<const float4*>(
                Ab + (size_t)(m0 + row) * lda + kk + kc4);
            As[kc4 + 0][row] = v.x;
            As[kc4 + 1][row] = v.y;
            As[kc4 + 2][row] = v.z;
            As[kc4 + 3][row] = v.w;
        }
        // ---- B tile: 16 k x 128 cols
#pragma unroll
        for (int u = 0; u < 2; ++u) {
            int f = tid + u * 256;
            int brow = f >> 5;               // 0..15
            int bc4  = (f & 31) * 4;         // 0..124
            *reinterpret_cast<float4*>(&Ws[brow][bc4]) =
                *reinterpret_cast<const float4*>(Bm + (size_t)(kt + brow) * ldb + n0 + bc4);
        }
        __syncthreads();

#pragma unroll
        for (int k = 0; k < 16; ++k) {
            float4 a0 = *reinterpret_cast<const float4*>(&As[k][tr * 8]);
            float4 a1 = *reinterpret_cast<const float4*>(&As[k][tr * 8 + 4]);
            float4 b0 = *reinterpret_cast<const float4*>(&Ws[k][tc * 8]);
            float4 b1 = *reinterpret_cast<const float4*>(&Ws[k][tc * 8 + 4]);
            unsigned long long bb0 = pack2(b0.x, b0.y);
            unsigned long long bb1 = pack2(b0.z, b0.w);
            unsigned long long bb2 = pack2(b1.x, b1.y);
            unsigned long long bb3 = pack2(b1.z, b1.w);
            float av[8] = {a0.x, a0.y, a0.z, a0.w, a1.x, a1.y, a1.z, a1.w};
#pragma unroll
            for (int i = 0; i < 8; ++i) {
                unsigned long long aa = pack2(av[i], av[i]);
                asm("fma.rn.f32x2 %0, %1, %2, %0;" : "+l"(acc[i][0]) : "l"(aa), "l"(bb0));
                asm("fma.rn.f32x2 %0, %1, %2, %0;" : "+l"(acc[i][1]) : "l"(aa), "l"(bb1));
                asm("fma.rn.f32x2 %0, %1, %2, %0;" : "+l"(acc[i][2]) : "l"(aa), "l"(bb2));
                asm("fma.rn.f32x2 %0, %1, %2, %0;" : "+l"(acc[i][3]) : "l"(aa), "l"(bb3));
            }
        }
        __syncthreads();
    }

    // ---- epilogue
#pragma unroll
    for (int i = 0; i < 8; ++i) {
        int row = m0 + tr * 8 + i;
#pragma unroll
        for (int jp = 0; jp < 4; ++jp) {
            float2 v = unpack2(acc[i][jp]);
            int col = n0 + tc * 8 + jp * 2;
            size_t o = (size_t)row * ldc + col;
            if (EPI == 0) {
                *reinterpret_cast<float2*>(&C[o]) = v;
            } else if (EPI == 1) {
                v.x += (row == col)     ? 1.0f : 0.0f;
                v.y += (row == col + 1) ? 1.0f : 0.0f;
                *reinterpret_cast<float2*>(&C[o]) = v;
            } else if (EPI == 2) {
                size_t xo = (size_t)row * 1024 + col;
                float gx = fminf(fmaxf(v.x - XRp[xo],     -1.0f), 1.0f);
                float gy = fminf(fmaxf(v.y - XRp[xo + 1], -1.0f), 1.0f);
                size_t ho = (size_t)row * ldh + col;
                float2 r;
                r.x = Hold[ho]     - ALPHA_C * gx;
                r.y = Hold[ho + 1] - ALPHA_C * gy;
                *reinterpret_cast<float2*>(&C[o]) = r;
            } else {
                float gx = fminf(fmaxf(v.x, -1.0f), 1.0f);
                float gy = fminf(fmaxf(v.y, -1.0f), 1.0f);
                size_t ho = (size_t)row * ldh + col;
                float2 r;
                r.x = Hold[ho]     - ALPHA_C * gx;
                r.y = Hold[ho + 1] - ALPHA_C * gy;
                *reinterpret_cast<float2*>(&C[o]) = r;
            }
        }
    }
}

} // namespace

extern "C" void kernel_launch(void* const* d_in, const int* in_sizes, int n_in,
                              void* d_out, int out_size)
{
    // Identify inputs by element count (robust to ordering).
    const float *x = nullptr, *W1 = nullptr, *W2 = nullptr, *h1 = nullptr, *h2 = nullptr;
    for (int i = 0; i < n_in; ++i) {
        switch (in_sizes[i]) {
            case 8388608: x  = (const float*)d_in[i]; break; // [4096,256,8]
            case 262144:  W1 = (const float*)d_in[i]; break; // [256,128,8]
            case 65536:   W2 = (const float*)d_in[i]; break; // [128,64,8]
            case 4194304: h1 = (const float*)d_in[i]; break; // [4096,128,8]
            case 2097152: h2 = (const float*)d_in[i]; break; // [4096,64,8]
        }
    }
    float* out = (float*)d_out;

    float *W1e, *W1re, *K1, *K2, *XR, *H1a, *H1b, *H2a, *H2b;
    cudaGetSymbolAddress((void**)&W1e,  g_W1e);
    cudaGetSymbolAddress((void**)&W1re, g_W1re);
    cudaGetSymbolAddress((void**)&K1,   g_K1);
    cudaGetSymbolAddress((void**)&K2,   g_K2);
    cudaGetSymbolAddress((void**)&XR,   g_XR);
    cudaGetSymbolAddress((void**)&H1a,  g_H1a);
    cudaGetSymbolAddress((void**)&H1b,  g_H1b);
    cudaGetSymbolAddress((void**)&H2a,  g_H2a);
    cudaGetSymbolAddress((void**)&H2b,  g_H2b);

    const int NOSPLIT = 0x40000000;

    // ---- weight expansion
    expand_kernel<<<(1024 * 2048 + 255) / 256, 256>>>(W1, 128, 256, W1e, 0,  1.0f);
    expand_kernel<<<(2048 * 1024 + 255) / 256, 256>>>(W1, 256, 128, W1re, 1, 1.0f);
    // K1 lower block = -What2  [512,1024]
    expand_kernel<<<(512 * 1024 + 255) / 256, 256>>>(W2, 64, 128, K1 + 1024 * 1024, 0, -1.0f);
    // K2 upper block = -What2r [1024,512]
    expand_kernel<<<(1024 * 512 + 255) / 256, 256>>>(W2, 128, 64, K2, 1, -1.0f);

    // ---- M1 + I -> K1 top  ([1024,1024], K=2048)
    gemm128<1><<<dim3(1024 / 128, 1024 / 128), 256>>>(
        W1e, nullptr, 2048, 0, NOSPLIT, W1re, 1024, K1, 1024, 2048, nullptr, nullptr, 0);
    // ---- M2 -> K2 bottom: (-What2) @ (-What2r) = What2 @ What2r  ([512,512], K=1024)
    gemm128<0><<<dim3(512 / 128, 512 / 128), 256>>>(
        K1 + 1024 * 1024, nullptr, 1024, 0, NOSPLIT, K2, 512, K2 + 1024 * 512, 512, 1024,
        nullptr, nullptr, 0);
    // ---- XR = x @ What1r  ([4096,1024], K=2048)
    gemm128<0><<<dim3(1024 / 128, 4096 / 128), 256>>>(
        x, nullptr, 2048, 0, NOSPLIT, W1re, 1024, XR, 1024, 2048, nullptr, nullptr, 0);

    // ---- init: out[0] = x (unchanged state), state buffers
    cudaMemcpyAsync(out, x, (size_t)4096 * 2048 * sizeof(float), cudaMemcpyDeviceToDevice, 0);
    cudaMemcpyAsync(H1a, h1, (size_t)4096 * 1024 * sizeof(float), cudaMemcpyDeviceToDevice, 0);
    cudaMemcpyAsync(H2a, h2, (size_t)4096 * 512 * sizeof(float), cudaMemcpyDeviceToDevice, 0);

    float* H1c = H1a; float* H1n = H1b;
    float* H2c = H2a; float* H2n = H2b;
    for (int it = 0; it < 20; ++it) {
        // H1' = H1 - a*clip([H1|H2]@K1 - XR)
        gemm128<2><<<dim3(1024 / 128, 4096 / 128), 256>>>(
            H1c, H2c, 1024, 512, 1024, K1, 1024, H1n, 1024, 1536, XR, H1c, 1024);
        // H2' = H2 - a*clip([H1'|H2]@K2)
        gemm128<3><<<dim3(512 / 128, 4096 / 128), 256>>>(
            H1n, H2c, 1024, 512, 1024, K2, 512, H2n, 512, 1536, nullptr, H2c, 512);
        float* t;
        t = H1c; H1c = H1n; H1n = t;
        t = H2c; H2c = H2n; H2n = t;
    }

    // ---- final outputs
    cudaMemcpyAsync(out + (size_t)4096 * 2048, H1c,
                    (size_t)4096 * 1024 * sizeof(float), cudaMemcpyDeviceToDevice, 0);
    cudaMemcpyAsync(out + (size_t)4096 * 2048 + (size_t)4096 * 1024, H2c,
                    (size_t)4096 * 512 * sizeof(float), cudaMemcpyDeviceToDevice, 0);
}

// round 5
// speedup vs baseline: 2.2625x; 2.2625x over previous
#include <cuda_runtime.h>
#include <cuda_bf16.h>
#include <cstdint>

namespace {

constexpr float ALPHA_C = 0.01f;
typedef __nv_bfloat16 bf;

__device__ __align__(1024) unsigned char g_pool[200u * 1024u * 1024u];

__device__ __forceinline__ uint32_t smem_u32(const void* p) {
    uint32_t a;
    asm("{ .reg .u64 t; cvta.to.shared.u64 t, %1; cvt.u32.u64 %0, t; }" : "=r"(a) : "l"(p));
    return a;
}
__device__ __forceinline__ void cp16(uint32_t s, const void* g) {
    asm volatile("cp.async.cg.shared.global [%0], [%1], 16;" :: "r"(s), "l"(g) : "memory");
}
#define CP_COMMIT() asm volatile("cp.async.commit_group;" ::: "memory")

#define LDSMX4(r, addr) \
    asm volatile("ldmatrix.sync.aligned.m8n8.x4.shared.b16 {%0,%1,%2,%3}, [%4];" \
        : "=r"((r)[0]), "=r"((r)[1]), "=r"((r)[2]), "=r"((r)[3]) : "r"(addr))
#define LDSMX4T(r, addr) \
    asm volatile("ldmatrix.sync.aligned.m8n8.x4.trans.shared.b16 {%0,%1,%2,%3}, [%4];" \
        : "=r"((r)[0]), "=r"((r)[1]), "=r"((r)[2]), "=r"((r)[3]) : "r"(addr))
#define MMA(c, a, b0, b1) \
    asm volatile("mma.sync.aligned.m16n8k16.row.col.f32.bf16.bf16.f32 " \
        "{%0,%1,%2,%3}, {%4,%5,%6,%7}, {%8,%9}, {%0,%1,%2,%3};" \
        : "+f"((c)[0]), "+f"((c)[1]), "+f"((c)[2]), "+f"((c)[3]) \
        : "r"((a)[0]), "r"((a)[1]), "r"((a)[2]), "r"((a)[3]), "r"(b0), "r"(b1))

// ---------------- Cayley expansion (byte-identical to validated R2) --------
__device__ __forceinline__ int reorder_sign(int a, int b) {
    int s = 0;
    int aa = a >> 1;
    while (aa) { s += __popc(aa & b); aa >>= 1; }
    return (s & 1) ? -1 : 1;
}
__global__ void expand_kernel(const float* __restrict__ W, int J, int I,
                              float* __restrict__ out, int rev, float sgn)
{
    int total = J * 8 * I * 8;
    int idx = blockIdx.x * blockDim.x + threadIdx.x;
    if (idx >= total) return;
    int ncol = I * 8;
    int col = idx % ncol;
    int row = idx / ncol;
    int a = row & 7, j = row >> 3;
    int c = col & 7, i = col >> 3;
    int e = a ^ c;
    float s = (float)reorder_sign(a, e) * sgn;
    size_t widx;
    if (rev) {
        int k = __popc(e);
        if ((k * (k - 1) / 2) & 1) s = -s;
        widx = (size_t)j * ncol + (size_t)i * 8 + e;
    } else {
        widx = (size_t)i * (size_t)(J * 8) + (size_t)j * 8 + e;
    }
    out[idx] = s * W[widx];
}

// ---------------- flat fp32 -> bf16 hi/lo packer ----------------
__global__ void pack_hi_lo(const float* __restrict__ s, long n,
                           bf* __restrict__ hi, bf* __restrict__ lo)
{
    long i = ((long)blockIdx.x * blockDim.x + threadIdx.x) * 4;
    if (i >= n) return;
    float4 v = *reinterpret_cast<const float4*>(s + i);
    bf h0 = __float2bfloat16(v.x), h1 = __float2bfloat16(v.y);
    bf h2 = __float2bfloat16(v.z), h3 = __float2bfloat16(v.w);
    bf l0 = __float2bfloat16(v.x - __bfloat162float(h0));
    bf l1 = __float2bfloat16(v.y - __bfloat162float(h1));
    bf l2 = __float2bfloat16(v.z - __bfloat162float(h2));
    bf l3 = __float2bfloat16(v.w - __bfloat162float(h3));
    __nv_bfloat162 hp0(h0, h1), hp1(h2, h3), lp0(l0, l1), lp1(l2, l3);
    uint2 hv = make_uint2(*(uint32_t*)&hp0, *(uint32_t*)&hp1);
    uint2 lv = make_uint2(*(uint32_t*)&lp0, *(uint32_t*)&lp1);
    *reinterpret_cast<uint2*>(hi + i) = hv;
    *reinterpret_cast<uint2*>(lo + i) = lv;
}

// ---------------------------------------------------------------------------
// bf16x3 mma.sync GEMM: C[m,n] = sum_k A[m,k]*B[k,n], A = [A0|A1] along K.
// Tiles: CTA 128x128x32, 8 warps of 64x32, double-buffered cp.async.
// EPI 0: Cf = acc                              (XR)
// EPI 1: g=clip(acc-XR); v=Hold-a*g; Cf,Ch,Cl  (H1 update)
// EPI 2: g=clip(acc);    v=Hold-a*g; Cf,Ch,Cl  (H2 update)
// EPI 3: v=acc(+I if addI); Ch,Cl only         (M1/M2 weights)
// ---------------------------------------------------------------------------
constexpr uint32_t A_BLK = 10240u;  // 128*40*2
constexpr uint32_t B_BLK = 8704u;   // 32*136*2
constexpr uint32_t B_BASE = 4u * A_BLK;               // 40960
constexpr uint32_t SMEM_BYTES = B_BASE + 4u * B_BLK;  // 75776

template <int EPI>
__global__ __launch_bounds__(256) void hgemm(
    const bf* __restrict__ A0h, const bf* __restrict__ A0l, int lda0,
    const bf* __restrict__ A1h, const bf* __restrict__ A1l, int lda1, int ksplit,
    const bf* __restrict__ Bh, const bf* __restrict__ Bl, int ldb, int K,
    float* __restrict__ Cf, int ldc,
    const float* __restrict__ XRp, const float* __restrict__ Hold,
    bf* __restrict__ Ch, bf* __restrict__ Cl, int addI)
{
    extern __shared__ unsigned char smdyn[];
    const uint32_t sbase = smem_u32(smdyn);
    const int tid = threadIdx.x;
    const int m0 = blockIdx.y * 128, n0 = blockIdx.x * 128;

    auto loadStage = [&](int s, int kt) {
        const bf *Ah, *Al;
        int lda, kk;
        if (kt < ksplit) { Ah = A0h; Al = A0l; lda = lda0; kk = kt; }
        else             { Ah = A1h; Al = A1l; lda = lda1; kk = kt - ksplit; }
#pragma unroll
        for (int j = 0; j < 2; ++j) {
            int t = tid + j * 256;
            int row = t >> 2, c = (t & 3) * 8;
            long go = (long)(m0 + row) * lda + kk + c;
            uint32_t so = sbase + (uint32_t)(s * 2) * A_BLK + (uint32_t)(row * 40 + c) * 2u;
            cp16(so, Ah + go);
            cp16(so + A_BLK, Al + go);
        }
#pragma unroll
        for (int j = 0; j < 2; ++j) {
            int t = tid + j * 256;
            int row = t >> 4, c = (t & 15) * 8;
            long go = (long)(kt + row) * ldb + n0 + c;
            uint32_t so = sbase + B_BASE + (uint32_t)(s * 2) * B_BLK + (uint32_t)(row * 136 + c) * 2u;
            cp16(so, Bh + go);
            cp16(so + B_BLK, Bl + go);
        }
        CP_COMMIT();
    };

    float acc[4][4][4];
#pragma unroll
    for (int i = 0; i < 4; ++i)
#pragma unroll
        for (int j = 0; j < 4; ++j)
#pragma unroll
            for (int q = 0; q < 4; ++q) acc[i][j][q] = 0.0f;

    const int lane = tid & 31, warp = tid >> 5;
    const int wm = (warp >> 2) * 64, wn = (warp & 3) * 32;
    const int NC = K / 32;

    loadStage(0, 0);
    for (int c = 0; c < NC; ++c) {
        if (c + 1 < NC) {
            loadStage((c + 1) & 1, (c + 1) * 32);
            asm volatile("cp.async.wait_group 1;" ::: "memory");
        } else {
            asm volatile("cp.async.wait_group 0;" ::: "memory");
        }
        __syncthreads();
        const int s = c & 1;
        const uint32_t aBase = sbase + (uint32_t)(s * 2) * A_BLK;
        const uint32_t bBase = sbase + B_BASE + (uint32_t)(s * 2) * B_BLK;
#pragma unroll
        for (int ks = 0; ks < 32; ks += 16) {
            uint32_t ah[4][4], al[4][4];
#pragma unroll
            for (int mi = 0; mi < 4; ++mi) {
                uint32_t ad = aBase +
                    (uint32_t)((wm + mi * 16 + (lane & 15)) * 40 + ks + (lane >> 4) * 8) * 2u;
                LDSMX4(ah[mi], ad);
                LDSMX4(al[mi], ad + A_BLK);
            }
            uint32_t bh[2][4], bl[2][4];
#pragma unroll
            for (int nj = 0; nj < 2; ++nj) {
                uint32_t bd = bBase +
                    (uint32_t)((ks + (lane & 15)) * 136 + wn + nj * 16 + (lane >> 4) * 8) * 2u;
                LDSMX4T(bh[nj], bd);
                LDSMX4T(bl[nj], bd + B_BLK);
            }
#pragma unroll
            for (int mi = 0; mi < 4; ++mi)
#pragma unroll
                for (int ni = 0; ni < 4; ++ni) {
                    uint32_t b0h = bh[ni >> 1][(ni & 1) * 2], b1h = bh[ni >> 1][(ni & 1) * 2 + 1];
                    uint32_t b0l = bl[ni >> 1][(ni & 1) * 2], b1l = bl[ni >> 1][(ni & 1) * 2 + 1];
                    MMA(acc[mi][ni], ah[mi], b0h, b1h);
                    MMA(acc[mi][ni], ah[mi], b0l, b1l);
                    MMA(acc[mi][ni], al[mi], b0h, b1h);
                }
        }
        __syncthreads();
    }

    // ---- fused epilogue ----
#pragma unroll
    for (int mi = 0; mi < 4; ++mi)
#pragma unroll
        for (int ni = 0; ni < 4; ++ni) {
            int col = n0 + wn + ni * 8 + (lane & 3) * 2;
#pragma unroll
            for (int h = 0; h < 2; ++h) {
                int row = m0 + wm + mi * 16 + (lane >> 2) + h * 8;
                float vx = acc[mi][ni][h * 2], vy = acc[mi][ni][h * 2 + 1];
                long o = (long)row * ldc + col;
                if (EPI == 1) { vx -= XRp[o]; vy -= XRp[o + 1]; }
                if (EPI == 1 || EPI == 2) {
                    vx = fminf(fmaxf(vx, -1.0f), 1.0f);
                    vy = fminf(fmaxf(vy, -1.0f), 1.0f);
                    vx = Hold[o]     - ALPHA_C * vx;
                    vy = Hold[o + 1] - ALPHA_C * vy;
                }
                if (EPI == 3 && addI) {
                    if (row == col)     vx += 1.0f;
                    if (row == col + 1) vy += 1.0f;
                }
                if (EPI != 3) *reinterpret_cast<float2*>(Cf + o) = make_float2(vx, vy);
                if (EPI != 0) {
                    bf hx = __float2bfloat16(vx), hy = __float2bfloat16(vy);
                    bf lx = __float2bfloat16(vx - __bfloat162float(hx));
                    bf ly = __float2bfloat16(vy - __bfloat162float(hy));
                    __nv_bfloat162 hp(hx, hy), lp(lx, ly);
                    *reinterpret_cast<uint32_t*>(Ch + o) = *(uint32_t*)&hp;
                    *reinterpret_cast<uint32_t*>(Cl + o) = *(uint32_t*)&lp;
                }
            }
        }
}

} // namespace

extern "C" void kernel_launch(void* const* d_in, const int* in_sizes, int n_in,
                              void* d_out, int out_size)
{
    const float *x = nullptr, *W1 = nullptr, *W2 = nullptr, *h1 = nullptr, *h2 = nullptr;
    for (int i = 0; i < n_in; ++i) {
        switch (in_sizes[i]) {
            case 8388608: x  = (const float*)d_in[i]; break;
            case 262144:  W1 = (const float*)d_in[i]; break;
            case 65536:   W2 = (const float*)d_in[i]; break;
            case 4194304: h1 = (const float*)d_in[i]; break;
            case 2097152: h2 = (const float*)d_in[i]; break;
        }
    }
    float* out = (float*)d_out;

    unsigned char* pool;
    cudaGetSymbolAddress((void**)&pool, g_pool);
    size_t off = 0;
    auto grab = [&](size_t bytes) -> void* {
        void* p = pool + off;
        off = (off + bytes + 1023) & ~(size_t)1023;
        return p;
    };
    // fp32 scratch
    float* W1e   = (float*)grab(8388608);   // What1   [1024,2048]
    float* W1re  = (float*)grab(8388608);   // What1r  [2048,1024]
    float* K1low = (float*)grab(2097152);   // -What2  [512,1024]
    float* K2top = (float*)grab(2097152);   // -What2r [1024,512]
    float* XR    = (float*)grab(16777216);  // [4096,1024]
    float* H1f[2] = {(float*)grab(16777216), (float*)grab(16777216)};
    float* H2f[2] = {(float*)grab(8388608),  (float*)grab(8388608)};
    // bf16 hi/lo row-major operands
    bf* xh   = (bf*)grab(16777216); bf* xl   = (bf*)grab(16777216);
    bf* W1eh = (bf*)grab(4194304);  bf* W1el = (bf*)grab(4194304);
    bf* W1rh = (bf*)grab(4194304);  bf* W1rl = (bf*)grab(4194304);
    bf* H1h[2] = {(bf*)grab(8388608), (bf*)grab(8388608)};
    bf* H1l[2] = {(bf*)grab(8388608), (bf*)grab(8388608)};
    bf* H2h[2] = {(bf*)grab(4194304), (bf*)grab(4194304)};
    bf* H2l[2] = {(bf*)grab(4194304), (bf*)grab(4194304)};
    bf* K1h = (bf*)grab(3145728);  bf* K1l = (bf*)grab(3145728);  // [1536,1024]
    bf* K2h = (bf*)grab(1572864);  bf* K2l = (bf*)grab(1572864);  // [1536,512]

    cudaFuncSetAttribute(hgemm<0>, cudaFuncAttributeMaxDynamicSharedMemorySize, SMEM_BYTES);
    cudaFuncSetAttribute(hgemm<1>, cudaFuncAttributeMaxDynamicSharedMemorySize, SMEM_BYTES);
    cudaFuncSetAttribute(hgemm<2>, cudaFuncAttributeMaxDynamicSharedMemorySize, SMEM_BYTES);
    cudaFuncSetAttribute(hgemm<3>, cudaFuncAttributeMaxDynamicSharedMemorySize, SMEM_BYTES);

    const int NOSPLIT = 0x40000000;

    // ---- expand Cayley-structured weights (fp32; validated R2) ----
    expand_kernel<<<8192, 256>>>(W1, 128, 256, W1e, 0, 1.0f);
    expand_kernel<<<8192, 256>>>(W1, 256, 128, W1re, 1, 1.0f);
    expand_kernel<<<2048, 256>>>(W2, 64, 128, K1low, 0, -1.0f);
    expand_kernel<<<2048, 256>>>(W2, 128, 64, K2top, 1, -1.0f);

    // ---- bf16 hi/lo packs (all row-major, flat) ----
    pack_hi_lo<<<8192, 256>>>(x,    8388608, xh, xl);
    pack_hi_lo<<<2048, 256>>>(W1e,  2097152, W1eh, W1el);
    pack_hi_lo<<<2048, 256>>>(W1re, 2097152, W1rh, W1rl);
    pack_hi_lo<<<4096, 256>>>(h1,   4194304, H1h[0], H1l[0]);
    pack_hi_lo<<<2048, 256>>>(h2,   2097152, H2h[0], H2l[0]);
    pack_hi_lo<<<512,  256>>>(K1low, 524288, K1h + 1024 * 1024, K1l + 1024 * 1024);
    pack_hi_lo<<<512,  256>>>(K2top, 524288, K2h, K2l);

    // ---- XR = x @ What1r  [4096,1024], K=2048 ----
    hgemm<0><<<dim3(8, 32), 256, SMEM_BYTES>>>(
        xh, xl, 2048, nullptr, nullptr, 0, NOSPLIT,
        W1rh, W1rl, 1024, 2048, XR, 1024, nullptr, nullptr, nullptr, nullptr, 0);
    // ---- K1 top = M1 + I = What1@What1r + I  [1024,1024], K=2048 ----
    hgemm<3><<<dim3(8, 8), 256, SMEM_BYTES>>>(
        W1eh, W1el, 2048, nullptr, nullptr, 0, NOSPLIT,
        W1rh, W1rl, 1024, 2048, nullptr, 1024, nullptr, nullptr, K1h, K1l, 1);
    // ---- K2 bottom = M2 = (-What2)@(-What2r)  [512,512], K=1024 ----
    hgemm<3><<<dim3(4, 4), 256, SMEM_BYTES>>>(
        K1h + 1024 * 1024, K1l + 1024 * 1024, 1024, nullptr, nullptr, 0, NOSPLIT,
        K2h, K2l, 512, 1024, nullptr, 512, nullptr, nullptr,
        K2h + 1024 * 512, K2l + 1024 * 512, 0);

    cudaMemcpyAsync(out, x, 33554432, cudaMemcpyDeviceToDevice, 0);
    float* out_h1 = out + 8388608;
    float* out_h2 = out + 12582912;

    for (int it = 0; it < 20; ++it) {
        int rd = it & 1, wr = 1 - rd;
        const float* Ho1 = it ? H1f[rd] : h1;
        const float* Ho2 = it ? H2f[rd] : h2;
        float* c1 = (it == 19) ? out_h1 : H1f[wr];
        float* c2 = (it == 19) ? out_h2 : H2f[wr];
        // H1' = Ho1 - a*clip([H1|H2]@K1 - XR)   [4096,1024], K=1536
        hgemm<1><<<dim3(8, 32), 256, SMEM_BYTES>>>(
            H1h[rd], H1l[rd], 1024, H2h[rd], H2l[rd], 512, 1024,
            K1h, K1l, 1024, 1536, c1, 1024, XR, Ho1, H1h[wr], H1l[wr], 0);
        // H2' = Ho2 - a*clip([H1'|H2]@K2)       [4096,512], K=1536
        hgemm<2><<<dim3(4, 32), 256, SMEM_BYTES>>>(
            H1h[wr], H1l[wr], 1024, H2h[rd], H2l[rd], 512, 1024,
            K2h, K2l, 512, 1536, c2, 512, nullptr, Ho2, H2h[wr], H2l[wr], 0);
    }
}

// round 6
// speedup vs baseline: 2.5593x; 1.1312x over previous
#include <cuda_runtime.h>
#include <cuda_bf16.h>
#include <cstdint>

namespace {

constexpr float ALPHA_C = 0.01f;
typedef __nv_bfloat16 bf;

__device__ __align__(1024) unsigned char g_pool[200u * 1024u * 1024u];

__device__ __forceinline__ uint32_t smem_u32(const void* p) {
    uint32_t a;
    asm("{ .reg .u64 t; cvta.to.shared.u64 t, %1; cvt.u32.u64 %0, t; }" : "=r"(a) : "l"(p));
    return a;
}
__device__ __forceinline__ void cp16(uint32_t s, const void* g) {
    asm volatile("cp.async.cg.shared.global [%0], [%1], 16;" :: "r"(s), "l"(g) : "memory");
}
#define CP_COMMIT() asm volatile("cp.async.commit_group;" ::: "memory")

#define LDSMX4(r, addr) \
    asm volatile("ldmatrix.sync.aligned.m8n8.x4.shared.b16 {%0,%1,%2,%3}, [%4];" \
        : "=r"((r)[0]), "=r"((r)[1]), "=r"((r)[2]), "=r"((r)[3]) : "r"(addr))
#define LDSMX4T(r, addr) \
    asm volatile("ldmatrix.sync.aligned.m8n8.x4.trans.shared.b16 {%0,%1,%2,%3}, [%4];" \
        : "=r"((r)[0]), "=r"((r)[1]), "=r"((r)[2]), "=r"((r)[3]) : "r"(addr))
#define MMA(c, a, b0, b1) \
    asm volatile("mma.sync.aligned.m16n8k16.row.col.f32.bf16.bf16.f32 " \
        "{%0,%1,%2,%3}, {%4,%5,%6,%7}, {%8,%9}, {%0,%1,%2,%3};" \
        : "+f"((c)[0]), "+f"((c)[1]), "+f"((c)[2]), "+f"((c)[3]) \
        : "r"((a)[0]), "r"((a)[1]), "r"((a)[2]), "r"((a)[3]), "r"(b0), "r"(b1))

// ---------------- Cayley expansion (validated R2) ----------------
__device__ __forceinline__ int reorder_sign(int a, int b) {
    int s = 0;
    int aa = a >> 1;
    while (aa) { s += __popc(aa & b); aa >>= 1; }
    return (s & 1) ? -1 : 1;
}
__global__ void expand_kernel(const float* __restrict__ W, int J, int I,
                              float* __restrict__ out, int rev, float sgn)
{
    int total = J * 8 * I * 8;
    int idx = blockIdx.x * blockDim.x + threadIdx.x;
    if (idx >= total) return;
    int ncol = I * 8;
    int col = idx % ncol;
    int row = idx / ncol;
    int a = row & 7, j = row >> 3;
    int c = col & 7, i = col >> 3;
    int e = a ^ c;
    float s = (float)reorder_sign(a, e) * sgn;
    size_t widx;
    if (rev) {
        int k = __popc(e);
        if ((k * (k - 1) / 2) & 1) s = -s;
        widx = (size_t)j * ncol + (size_t)i * 8 + e;
    } else {
        widx = (size_t)i * (size_t)(J * 8) + (size_t)j * 8 + e;
    }
    out[idx] = s * W[widx];
}

// ---------------- flat fp32 -> bf16 hi/lo packer ----------------
__global__ void pack_hi_lo(const float* __restrict__ s, long n,
                           bf* __restrict__ hi, bf* __restrict__ lo)
{
    long i = ((long)blockIdx.x * blockDim.x + threadIdx.x) * 4;
    if (i >= n) return;
    float4 v = *reinterpret_cast<const float4*>(s + i);
    bf h0 = __float2bfloat16(v.x), h1 = __float2bfloat16(v.y);
    bf h2 = __float2bfloat16(v.z), h3 = __float2bfloat16(v.w);
    bf l0 = __float2bfloat16(v.x - __bfloat162float(h0));
    bf l1 = __float2bfloat16(v.y - __bfloat162float(h1));
    bf l2 = __float2bfloat16(v.z - __bfloat162float(h2));
    bf l3 = __float2bfloat16(v.w - __bfloat162float(h3));
    __nv_bfloat162 hp0(h0, h1), hp1(h2, h3), lp0(l0, l1), lp1(l2, l3);
    uint2 hv = make_uint2(*(uint32_t*)&hp0, *(uint32_t*)&hp1);
    uint2 lv = make_uint2(*(uint32_t*)&lp0, *(uint32_t*)&lp1);
    *reinterpret_cast<uint2*>(hi + i) = hv;
    *reinterpret_cast<uint2*>(lo + i) = lv;
}

// ---------------------------------------------------------------------------
// bf16x3 mma.sync GEMM: C[m,n] = sum_k A[m,k]*B[k,n], A=[A0|A1] along K.
// CTA tile 128 x BN, 8 warps (2M x 4N) of 64 x BN/4. 3-stage cp.async,
// ONE __syncthreads per 32-k chunk. Fragment sequencing: a0*bh, a1*bh, a0*bl.
// EPI 0: Cf = acc                              (XR)
// EPI 1: g=clip(acc-XR); v=Hold-a*g; Cf,Ch,Cl  (H1 update)
// EPI 2: g=clip(acc);    v=Hold-a*g; Cf,Ch,Cl  (H2 update)
// EPI 3: v=acc(+I if addI); Ch,Cl only         (M1/M2 weights)
// ---------------------------------------------------------------------------
template <int EPI, int BN>
__global__ __launch_bounds__(256, 1) void hgemm(
    const bf* __restrict__ A0h, const bf* __restrict__ A0l, int lda0,
    const bf* __restrict__ A1h, const bf* __restrict__ A1l, int lda1, int ksplit,
    const bf* __restrict__ Bh, const bf* __restrict__ Bl, int ldb, int K,
    float* __restrict__ Cf, int ldc,
    const float* __restrict__ XRp, const float* __restrict__ Hold,
    bf* __restrict__ Ch, bf* __restrict__ Cl, int addI)
{
    constexpr int WN  = BN / 4;        // warp N tile
    constexpr int NFR = WN / 8;        // n8 fragments per warp
    constexpr int NL  = NFR / 2;       // ldmatrix.x4T per operand
    constexpr uint32_t BST   = BN + 8; // B smem stride (elems)
    constexpr uint32_t A_BLK = 10240u; // 128*40*2
    constexpr uint32_t B_BLK = 32u * BST * 2u;
    constexpr uint32_t STAGE = 2u * A_BLK + 2u * B_BLK;
    constexpr int CPT = BN / 64;       // B cp16s per thread per operand
    constexpr int BROW = BN / 8;       // cp16s per B row

    extern __shared__ unsigned char smdyn[];
    const uint32_t sbase = smem_u32(smdyn);
    const int tid = threadIdx.x;
    const int m0 = blockIdx.y * 128, n0 = blockIdx.x * BN;

    auto loadStage = [&](int s, int kt) {
        const bf *Ah, *Al;
        int lda, kk;
        if (kt < ksplit) { Ah = A0h; Al = A0l; lda = lda0; kk = kt; }
        else             { Ah = A1h; Al = A1l; lda = lda1; kk = kt - ksplit; }
        const uint32_t sa = sbase + (uint32_t)s * STAGE;
#pragma unroll
        for (int j = 0; j < 2; ++j) {
            int t = tid + j * 256;
            int row = t >> 2, c = (t & 3) * 8;
            long go = (long)(m0 + row) * lda + kk + c;
            uint32_t so = sa + (uint32_t)(row * 40 + c) * 2u;
            cp16(so, Ah + go);
            cp16(so + A_BLK, Al + go);
        }
        const uint32_t sb = sa + 2u * A_BLK;
#pragma unroll
        for (int j = 0; j < CPT; ++j) {
            int t = tid + j * 256;
            int row = t / BROW, c = (t % BROW) * 8;
            long go = (long)(kt + row) * ldb + n0 + c;
            uint32_t so = sb + (uint32_t)(row * BST + c) * 2u;
            cp16(so, Bh + go);
            cp16(so + B_BLK, Bl + go);
        }
        CP_COMMIT();
    };

    float acc[4][NFR][4];
#pragma unroll
    for (int i = 0; i < 4; ++i)
#pragma unroll
        for (int j = 0; j < NFR; ++j)
#pragma unroll
            for (int q = 0; q < 4; ++q) acc[i][j][q] = 0.0f;

    const int lane = tid & 31, warp = tid >> 5;
    const int wm = (warp >> 2) * 64, wn = (warp & 3) * WN;
    const int NC = K / 32;

    loadStage(0, 0);
    loadStage(1, 32);

    for (int c = 0; c < NC; ++c) {
        asm volatile("cp.async.wait_group 1;" ::: "memory");
        __syncthreads();
        if (c + 2 < NC) loadStage((c + 2) % 3, (c + 2) * 32);
        else CP_COMMIT();  // keep group accounting uniform

        const uint32_t aB = sbase + (uint32_t)(c % 3) * STAGE;
        const uint32_t bB = aB + 2u * A_BLK;
#pragma unroll
        for (int ks = 0; ks < 32; ks += 16) {
            uint32_t a0[4][4], a1[4][4], bh[NL][4], bl[NL][4];
#pragma unroll
            for (int mi = 0; mi < 4; ++mi) {
                uint32_t ad = aB +
                    (uint32_t)((wm + mi * 16 + (lane & 15)) * 40 + ks + (lane >> 4) * 8) * 2u;
                LDSMX4(a0[mi], ad);
            }
#pragma unroll
            for (int nj = 0; nj < NL; ++nj) {
                uint32_t bd = bB +
                    (uint32_t)((ks + (lane & 15)) * BST + wn + nj * 16 + (lane >> 4) * 8) * 2u;
                LDSMX4T(bh[nj], bd);
            }
#pragma unroll
            for (int mi = 0; mi < 4; ++mi)
#pragma unroll
                for (int ni = 0; ni < NFR; ++ni)
                    MMA(acc[mi][ni], a0[mi], bh[ni >> 1][(ni & 1) * 2], bh[ni >> 1][(ni & 1) * 2 + 1]);
#pragma unroll
            for (int mi = 0; mi < 4; ++mi) {
                uint32_t ad = aB + A_BLK +
                    (uint32_t)((wm + mi * 16 + (lane & 15)) * 40 + ks + (lane >> 4) * 8) * 2u;
                LDSMX4(a1[mi], ad);
            }
#pragma unroll
            for (int mi = 0; mi < 4; ++mi)
#pragma unroll
                for (int ni = 0; ni < NFR; ++ni)
                    MMA(acc[mi][ni], a1[mi], bh[ni >> 1][(ni & 1) * 2], bh[ni >> 1][(ni & 1) * 2 + 1]);
#pragma unroll
            for (int nj = 0; nj < NL; ++nj) {
                uint32_t bd = bB + B_BLK +
                    (uint32_t)((ks + (lane & 15)) * BST + wn + nj * 16 + (lane >> 4) * 8) * 2u;
                LDSMX4T(bl[nj], bd);
            }
#pragma unroll
            for (int mi = 0; mi < 4; ++mi)
#pragma unroll
                for (int ni = 0; ni < NFR; ++ni)
                    MMA(acc[mi][ni], a0[mi], bl[ni >> 1][(ni & 1) * 2], bl[ni >> 1][(ni & 1) * 2 + 1]);
        }
    }

    // ---- fused epilogue ----
#pragma unroll
    for (int mi = 0; mi < 4; ++mi)
#pragma unroll
        for (int ni = 0; ni < NFR; ++ni) {
            int col = n0 + wn + ni * 8 + (lane & 3) * 2;
#pragma unroll
            for (int h = 0; h < 2; ++h) {
                int row = m0 + wm + mi * 16 + (lane >> 2) + h * 8;
                float vx = acc[mi][ni][h * 2], vy = acc[mi][ni][h * 2 + 1];
                long o = (long)row * ldc + col;
                if (EPI == 1) { vx -= XRp[o]; vy -= XRp[o + 1]; }
                if (EPI == 1 || EPI == 2) {
                    vx = fminf(fmaxf(vx, -1.0f), 1.0f);
                    vy = fminf(fmaxf(vy, -1.0f), 1.0f);
                    vx = Hold[o]     - ALPHA_C * vx;
                    vy = Hold[o + 1] - ALPHA_C * vy;
                }
                if (EPI == 3 && addI) {
                    if (row == col)     vx += 1.0f;
                    if (row == col + 1) vy += 1.0f;
                }
                if (EPI != 3) *reinterpret_cast<float2*>(Cf + o) = make_float2(vx, vy);
                if (EPI != 0) {
                    bf hx = __float2bfloat16(vx), hy = __float2bfloat16(vy);
                    bf lx = __float2bfloat16(vx - __bfloat162float(hx));
                    bf ly = __float2bfloat16(vy - __bfloat162float(hy));
                    __nv_bfloat162 hp(hx, hy), lp(lx, ly);
                    *reinterpret_cast<uint32_t*>(Ch + o) = *(uint32_t*)&hp;
                    *reinterpret_cast<uint32_t*>(Cl + o) = *(uint32_t*)&lp;
                }
            }
        }
}

template <int BN>
constexpr uint32_t smemBytes() {
    return 3u * (2u * 10240u + 2u * (32u * (BN + 8u) * 2u));
}

} // namespace

extern "C" void kernel_launch(void* const* d_in, const int* in_sizes, int n_in,
                              void* d_out, int out_size)
{
    const float *x = nullptr, *W1 = nullptr, *W2 = nullptr, *h1 = nullptr, *h2 = nullptr;
    for (int i = 0; i < n_in; ++i) {
        switch (in_sizes[i]) {
            case 8388608: x  = (const float*)d_in[i]; break;
            case 262144:  W1 = (const float*)d_in[i]; break;
            case 65536:   W2 = (const float*)d_in[i]; break;
            case 4194304: h1 = (const float*)d_in[i]; break;
            case 2097152: h2 = (const float*)d_in[i]; break;
        }
    }
    float* out = (float*)d_out;

    unsigned char* pool;
    cudaGetSymbolAddress((void**)&pool, g_pool);
    size_t off = 0;
    auto grab = [&](size_t bytes) -> void* {
        void* p = pool + off;
        off = (off + bytes + 1023) & ~(size_t)1023;
        return p;
    };
    float* W1e   = (float*)grab(8388608);
    float* W1re  = (float*)grab(8388608);
    float* K1low = (float*)grab(2097152);
    float* K2top = (float*)grab(2097152);
    float* XR    = (float*)grab(16777216);
    float* H1f[2] = {(float*)grab(16777216), (float*)grab(16777216)};
    float* H2f[2] = {(float*)grab(8388608),  (float*)grab(8388608)};
    bf* xh   = (bf*)grab(16777216); bf* xl   = (bf*)grab(16777216);
    bf* W1eh = (bf*)grab(4194304);  bf* W1el = (bf*)grab(4194304);
    bf* W1rh = (bf*)grab(4194304);  bf* W1rl = (bf*)grab(4194304);
    bf* H1h[2] = {(bf*)grab(8388608), (bf*)grab(8388608)};
    bf* H1l[2] = {(bf*)grab(8388608), (bf*)grab(8388608)};
    bf* H2h[2] = {(bf*)grab(4194304), (bf*)grab(4194304)};
    bf* H2l[2] = {(bf*)grab(4194304), (bf*)grab(4194304)};
    bf* K1h = (bf*)grab(3145728);  bf* K1l = (bf*)grab(3145728);
    bf* K2h = (bf*)grab(1572864);  bf* K2l = (bf*)grab(1572864);

    cudaFuncSetAttribute(hgemm<0, 256>, cudaFuncAttributeMaxDynamicSharedMemorySize, smemBytes<256>());
    cudaFuncSetAttribute(hgemm<1, 256>, cudaFuncAttributeMaxDynamicSharedMemorySize, smemBytes<256>());
    cudaFuncSetAttribute(hgemm<2, 128>, cudaFuncAttributeMaxDynamicSharedMemorySize, smemBytes<128>());
    cudaFuncSetAttribute(hgemm<3, 64>,  cudaFuncAttributeMaxDynamicSharedMemorySize, smemBytes<64>());

    const int NOSPLIT = 0x40000000;

    expand_kernel<<<8192, 256>>>(W1, 128, 256, W1e, 0, 1.0f);
    expand_kernel<<<8192, 256>>>(W1, 256, 128, W1re, 1, 1.0f);
    expand_kernel<<<2048, 256>>>(W2, 64, 128, K1low, 0, -1.0f);
    expand_kernel<<<2048, 256>>>(W2, 128, 64, K2top, 1, -1.0f);

    pack_hi_lo<<<8192, 256>>>(x,    8388608, xh, xl);
    pack_hi_lo<<<2048, 256>>>(W1e,  2097152, W1eh, W1el);
    pack_hi_lo<<<2048, 256>>>(W1re, 2097152, W1rh, W1rl);
    pack_hi_lo<<<4096, 256>>>(h1,   4194304, H1h[0], H1l[0]);
    pack_hi_lo<<<2048, 256>>>(h2,   2097152, H2h[0], H2l[0]);
    pack_hi_lo<<<512,  256>>>(K1low, 524288, K1h + 1024 * 1024, K1l + 1024 * 1024);
    pack_hi_lo<<<512,  256>>>(K2top, 524288, K2h, K2l);

    // XR = x @ What1r  [4096,1024], K=2048
    hgemm<0, 256><<<dim3(4, 32), 256, smemBytes<256>()>>>(
        xh, xl, 2048, nullptr, nullptr, 0, NOSPLIT,
        W1rh, W1rl, 1024, 2048, XR, 1024, nullptr, nullptr, nullptr, nullptr, 0);
    // K1 top = What1@What1r + I  [1024,1024], K=2048
    hgemm<3, 64><<<dim3(16, 8), 256, smemBytes<64>()>>>(
        W1eh, W1el, 2048, nullptr, nullptr, 0, NOSPLIT,
        W1rh, W1rl, 1024, 2048, nullptr, 1024, nullptr, nullptr, K1h, K1l, 1);
    // K2 bottom = (-What2)@(-What2r)  [512,512], K=1024
    hgemm<3, 64><<<dim3(8, 4), 256, smemBytes<64>()>>>(
        K1h + 1024 * 1024, K1l + 1024 * 1024, 1024, nullptr, nullptr, 0, NOSPLIT,
        K2h, K2l, 512, 1024, nullptr, 512, nullptr, nullptr,
        K2h + 1024 * 512, K2l + 1024 * 512, 0);

    cudaMemcpyAsync(out, x, 33554432, cudaMemcpyDeviceToDevice, 0);
    float* out_h1 = out + 8388608;
    float* out_h2 = out + 12582912;

    for (int it = 0; it < 20; ++it) {
        int rd = it & 1, wr = 1 - rd;
        const float* Ho1 = it ? H1f[rd] : h1;
        const float* Ho2 = it ? H2f[rd] : h2;
        float* c1 = (it == 19) ? out_h1 : H1f[wr];
        float* c2 = (it == 19) ? out_h2 : H2f[wr];
        // H1' = Ho1 - a*clip([H1|H2]@K1 - XR)   [4096,1024], K=1536
        hgemm<1, 256><<<dim3(4, 32), 256, smemBytes<256>()>>>(
            H1h[rd], H1l[rd], 1024, H2h[rd], H2l[rd], 512, 1024,
            K1h, K1l, 1024, 1536, c1, 1024, XR, Ho1, H1h[wr], H1l[wr], 0);
        // H2' = Ho2 - a*clip([H1'|H2]@K2)       [4096,512], K=1536
        hgemm<2, 128><<<dim3(4, 32), 256, smemBytes<128>()>>>(
            H1h[wr], H1l[wr], 1024, H2h[rd], H2l[rd], 512, 1024,
            K2h, K2l, 512, 1536, c2, 512, nullptr, Ho2, H2h[wr], H2l[wr], 0);
    }
}

// round 7
// speedup vs baseline: 2.5627x; 1.0013x over previous
#include <cuda_runtime.h>
#include <cuda_bf16.h>
#include <cstdint>

namespace {

constexpr float ALPHA_C = 0.01f;
typedef __nv_bfloat16 bf;

__device__ __align__(1024) unsigned char g_pool[200u * 1024u * 1024u];

__device__ __forceinline__ uint32_t smem_u32(const void* p) {
    uint32_t a;
    asm("{ .reg .u64 t; cvta.to.shared.u64 t, %1; cvt.u32.u64 %0, t; }" : "=r"(a) : "l"(p));
    return a;
}
__device__ __forceinline__ void cp16(uint32_t s, const void* g) {
    asm volatile("cp.async.cg.shared.global [%0], [%1], 16;" :: "r"(s), "l"(g) : "memory");
}
#define CP_COMMIT() asm volatile("cp.async.commit_group;" ::: "memory")

#define LDSMX4(r, addr) \
    asm volatile("ldmatrix.sync.aligned.m8n8.x4.shared.b16 {%0,%1,%2,%3}, [%4];" \
        : "=r"((r)[0]), "=r"((r)[1]), "=r"((r)[2]), "=r"((r)[3]) : "r"(addr))
#define LDSMX4T(r, addr) \
    asm volatile("ldmatrix.sync.aligned.m8n8.x4.trans.shared.b16 {%0,%1,%2,%3}, [%4];" \
        : "=r"((r)[0]), "=r"((r)[1]), "=r"((r)[2]), "=r"((r)[3]) : "r"(addr))
#define MMA(c, a, b0, b1) \
    asm volatile("mma.sync.aligned.m16n8k16.row.col.f32.bf16.bf16.f32 " \
        "{%0,%1,%2,%3}, {%4,%5,%6,%7}, {%8,%9}, {%0,%1,%2,%3};" \
        : "+f"((c)[0]), "+f"((c)[1]), "+f"((c)[2]), "+f"((c)[3]) \
        : "r"((a)[0]), "r"((a)[1]), "r"((a)[2]), "r"((a)[3]), "r"(b0), "r"(b1))

// ---------------- fused Cayley expansion (4 jobs, validated math) ----------
struct ExpandJobs {
    const float* W[4];
    float* out[4];
    int J[4], I[4], rev[4];
    float sgn[4];
    int start[5];
};
__device__ __forceinline__ int reorder_sign(int a, int b) {
    int s = 0;
    int aa = a >> 1;
    while (aa) { s += __popc(aa & b); aa >>= 1; }
    return (s & 1) ? -1 : 1;
}
__global__ void expand_fused(ExpandJobs E)
{
    int blk = blockIdx.x, jb = 0;
#pragma unroll
    for (int t = 1; t < 4; ++t) if (blk >= E.start[t]) jb = t;
    int J = E.J[jb], I = E.I[jb];
    int idx = (blk - E.start[jb]) * 256 + threadIdx.x;
    int ncol = I * 8;
    int col = idx % ncol;
    int row = idx / ncol;
    int a = row & 7, j = row >> 3;
    int c = col & 7, i = col >> 3;
    int e = a ^ c;
    float s = (float)reorder_sign(a, e) * E.sgn[jb];
    size_t widx;
    if (E.rev[jb]) {
        int k = __popc(e);
        if ((k * (k - 1) / 2) & 1) s = -s;
        widx = (size_t)j * ncol + (size_t)i * 8 + e;
    } else {
        widx = (size_t)i * (size_t)(J * 8) + (size_t)j * 8 + e;
    }
    E.out[jb][idx] = s * E.W[jb][widx];
}

// ---------------- fused fp32 -> bf16 hi/lo packer (7 jobs) ----------------
struct PackJobs {
    const float* src[7];
    bf* hi[7];
    bf* lo[7];
    int start[8];
};
__global__ void pack_fused(PackJobs P)
{
    int blk = blockIdx.x, jb = 0;
#pragma unroll
    for (int t = 1; t < 7; ++t) if (blk >= P.start[t]) jb = t;
    long i = ((long)(blk - P.start[jb]) * 256 + threadIdx.x) * 4;
    float4 v = *reinterpret_cast<const float4*>(P.src[jb] + i);
    bf h0 = __float2bfloat16(v.x), h1 = __float2bfloat16(v.y);
    bf h2 = __float2bfloat16(v.z), h3 = __float2bfloat16(v.w);
    bf l0 = __float2bfloat16(v.x - __bfloat162float(h0));
    bf l1 = __float2bfloat16(v.y - __bfloat162float(h1));
    bf l2 = __float2bfloat16(v.z - __bfloat162float(h2));
    bf l3 = __float2bfloat16(v.w - __bfloat162float(h3));
    __nv_bfloat162 hp0(h0, h1), hp1(h2, h3), lp0(l0, l1), lp1(l2, l3);
    *reinterpret_cast<uint2*>(P.hi[jb] + i) = make_uint2(*(uint32_t*)&hp0, *(uint32_t*)&hp1);
    *reinterpret_cast<uint2*>(P.lo[jb] + i) = make_uint2(*(uint32_t*)&lp0, *(uint32_t*)&lp1);
}

// ---------------------------------------------------------------------------
// bf16x3 mma.sync GEMM: C[m,n] = sum_k A[m,k]*B[k,n], A=[A0|A1] along K.
// CTA tile 128 x BN, 8 warps (2M x 4N). 3-stage cp.async, one sync per chunk.
// State is bf16 hi/lo pairs; fp32 written only when Cf != nullptr.
// EPI 0: Cf = acc                                        (XR)
// EPI 1: g=clip(acc-XR); v=(Hh+Hl)-a*g; [Cf],[Ch/Cl]     (H1 update)
// EPI 2: g=clip(acc);    v=(Hh+Hl)-a*g; [Cf],[Ch/Cl]     (H2 update)
// EPI 3: v=acc(+I if addI); Ch/Cl                        (M1/M2 weights)
// ---------------------------------------------------------------------------
template <int EPI, int BN>
__global__ __launch_bounds__(256, 1) void hgemm(
    const bf* __restrict__ A0h, const bf* __restrict__ A0l, int lda0,
    const bf* __restrict__ A1h, const bf* __restrict__ A1l, int lda1, int ksplit,
    const bf* __restrict__ Bh, const bf* __restrict__ Bl, int ldb, int K,
    float* __restrict__ Cf, int ldc,
    const float* __restrict__ XRp,
    const bf* __restrict__ Hh, const bf* __restrict__ Hl,
    bf* __restrict__ Ch, bf* __restrict__ Cl, int addI)
{
    constexpr int WN  = BN / 4;
    constexpr int NFR = WN / 8;
    constexpr int NL  = NFR / 2;
    constexpr uint32_t BST   = BN + 8;
    constexpr uint32_t A_BLK = 10240u;
    constexpr uint32_t B_BLK = 32u * BST * 2u;
    constexpr uint32_t STAGE = 2u * A_BLK + 2u * B_BLK;
    constexpr int CPT = BN / 64;
    constexpr int BROW = BN / 8;

    extern __shared__ unsigned char smdyn[];
    const uint32_t sbase = smem_u32(smdyn);
    const int tid = threadIdx.x;
    const int m0 = blockIdx.y * 128, n0 = blockIdx.x * BN;

    auto loadStage = [&](int s, int kt) {
        const bf *Ah, *Al;
        int lda, kk;
        if (kt < ksplit) { Ah = A0h; Al = A0l; lda = lda0; kk = kt; }
        else             { Ah = A1h; Al = A1l; lda = lda1; kk = kt - ksplit; }
        const uint32_t sa = sbase + (uint32_t)s * STAGE;
#pragma unroll
        for (int j = 0; j < 2; ++j) {
            int t = tid + j * 256;
            int row = t >> 2, c = (t & 3) * 8;
            long go = (long)(m0 + row) * lda + kk + c;
            uint32_t so = sa + (uint32_t)(row * 40 + c) * 2u;
            cp16(so, Ah + go);
            cp16(so + A_BLK, Al + go);
        }
        const uint32_t sb = sa + 2u * A_BLK;
#pragma unroll
        for (int j = 0; j < CPT; ++j) {
            int t = tid + j * 256;
            int row = t / BROW, c = (t % BROW) * 8;
            long go = (long)(kt + row) * ldb + n0 + c;
            uint32_t so = sb + (uint32_t)(row * BST + c) * 2u;
            cp16(so, Bh + go);
            cp16(so + B_BLK, Bl + go);
        }
        CP_COMMIT();
    };

    float acc[4][NFR][4];
#pragma unroll
    for (int i = 0; i < 4; ++i)
#pragma unroll
        for (int j = 0; j < NFR; ++j)
#pragma unroll
            for (int q = 0; q < 4; ++q) acc[i][j][q] = 0.0f;

    const int lane = tid & 31, warp = tid >> 5;
    const int wm = (warp >> 2) * 64, wn = (warp & 3) * WN;
    const int NC = K / 32;

    loadStage(0, 0);
    loadStage(1, 32);

    for (int c = 0; c < NC; ++c) {
        asm volatile("cp.async.wait_group 1;" ::: "memory");
        __syncthreads();
        if (c + 2 < NC) loadStage((c + 2) % 3, (c + 2) * 32);
        else CP_COMMIT();

        const uint32_t aB = sbase + (uint32_t)(c % 3) * STAGE;
        const uint32_t bB = aB + 2u * A_BLK;
#pragma unroll
        for (int ks = 0; ks < 32; ks += 16) {
            uint32_t a0[4][4], a1[4][4], bh[NL][4], bl[NL][4];
#pragma unroll
            for (int mi = 0; mi < 4; ++mi) {
                uint32_t ad = aB +
                    (uint32_t)((wm + mi * 16 + (lane & 15)) * 40 + ks + (lane >> 4) * 8) * 2u;
                LDSMX4(a0[mi], ad);
            }
#pragma unroll
            for (int nj = 0; nj < NL; ++nj) {
                uint32_t bd = bB +
                    (uint32_t)((ks + (lane & 15)) * BST + wn + nj * 16 + (lane >> 4) * 8) * 2u;
                LDSMX4T(bh[nj], bd);
            }
#pragma unroll
            for (int mi = 0; mi < 4; ++mi)
#pragma unroll
                for (int ni = 0; ni < NFR; ++ni)
                    MMA(acc[mi][ni], a0[mi], bh[ni >> 1][(ni & 1) * 2], bh[ni >> 1][(ni & 1) * 2 + 1]);
#pragma unroll
            for (int mi = 0; mi < 4; ++mi) {
                uint32_t ad = aB + A_BLK +
                    (uint32_t)((wm + mi * 16 + (lane & 15)) * 40 + ks + (lane >> 4) * 8) * 2u;
                LDSMX4(a1[mi], ad);
            }
#pragma unroll
            for (int mi = 0; mi < 4; ++mi)
#pragma unroll
                for (int ni = 0; ni < NFR; ++ni)
                    MMA(acc[mi][ni], a1[mi], bh[ni >> 1][(ni & 1) * 2], bh[ni >> 1][(ni & 1) * 2 + 1]);
#pragma unroll
            for (int nj = 0; nj < NL; ++nj) {
                uint32_t bd = bB + B_BLK +
                    (uint32_t)((ks + (lane & 15)) * BST + wn + nj * 16 + (lane >> 4) * 8) * 2u;
                LDSMX4T(bl[nj], bd);
            }
#pragma unroll
            for (int mi = 0; mi < 4; ++mi)
#pragma unroll
                for (int ni = 0; ni < NFR; ++ni)
                    MMA(acc[mi][ni], a0[mi], bl[ni >> 1][(ni & 1) * 2], bl[ni >> 1][(ni & 1) * 2 + 1]);
        }
    }

    // ---- fused epilogue ----
#pragma unroll
    for (int mi = 0; mi < 4; ++mi)
#pragma unroll
        for (int ni = 0; ni < NFR; ++ni) {
            int col = n0 + wn + ni * 8 + (lane & 3) * 2;
#pragma unroll
            for (int h = 0; h < 2; ++h) {
                int row = m0 + wm + mi * 16 + (lane >> 2) + h * 8;
                float vx = acc[mi][ni][h * 2], vy = acc[mi][ni][h * 2 + 1];
                long o = (long)row * ldc + col;
                if (EPI == 1) { vx -= XRp[o]; vy -= XRp[o + 1]; }
                if (EPI == 1 || EPI == 2) {
                    vx = fminf(fmaxf(vx, -1.0f), 1.0f);
                    vy = fminf(fmaxf(vy, -1.0f), 1.0f);
                    __nv_bfloat162 hh = *reinterpret_cast<const __nv_bfloat162*>(Hh + o);
                    __nv_bfloat162 ll = *reinterpret_cast<const __nv_bfloat162*>(Hl + o);
                    vx = (__bfloat162float(hh.x) + __bfloat162float(ll.x)) - ALPHA_C * vx;
                    vy = (__bfloat162float(hh.y) + __bfloat162float(ll.y)) - ALPHA_C * vy;
                }
                if (EPI == 3 && addI) {
                    if (row == col)     vx += 1.0f;
                    if (row == col + 1) vy += 1.0f;
                }
                if (EPI == 0 || ((EPI == 1 || EPI == 2) && Cf))
                    *reinterpret_cast<float2*>(Cf + o) = make_float2(vx, vy);
                if (EPI == 3 || ((EPI == 1 || EPI == 2) && Ch)) {
                    bf hx = __float2bfloat16(vx), hy = __float2bfloat16(vy);
                    bf lx = __float2bfloat16(vx - __bfloat162float(hx));
                    bf ly = __float2bfloat16(vy - __bfloat162float(hy));
                    __nv_bfloat162 hp(hx, hy), lp(lx, ly);
                    *reinterpret_cast<uint32_t*>(Ch + o) = *(uint32_t*)&hp;
                    *reinterpret_cast<uint32_t*>(Cl + o) = *(uint32_t*)&lp;
                }
            }
        }
}

template <int BN>
constexpr uint32_t smemBytes() {
    return 3u * (2u * 10240u + 2u * (32u * (BN + 8u) * 2u));
}

} // namespace

extern "C" void kernel_launch(void* const* d_in, const int* in_sizes, int n_in,
                              void* d_out, int out_size)
{
    const float *x = nullptr, *W1 = nullptr, *W2 = nullptr, *h1 = nullptr, *h2 = nullptr;
    for (int i = 0; i < n_in; ++i) {
        switch (in_sizes[i]) {
            case 8388608: x  = (const float*)d_in[i]; break;
            case 262144:  W1 = (const float*)d_in[i]; break;
            case 65536:   W2 = (const float*)d_in[i]; break;
            case 4194304: h1 = (const float*)d_in[i]; break;
            case 2097152: h2 = (const float*)d_in[i]; break;
        }
    }
    float* out = (float*)d_out;

    unsigned char* pool;
    cudaGetSymbolAddress((void**)&pool, g_pool);
    size_t off = 0;
    auto grab = [&](size_t bytes) -> void* {
        void* p = pool + off;
        off = (off + bytes + 1023) & ~(size_t)1023;
        return p;
    };
    float* W1e   = (float*)grab(8388608);
    float* W1re  = (float*)grab(8388608);
    float* K1low = (float*)grab(2097152);
    float* K2top = (float*)grab(2097152);
    float* XR    = (float*)grab(16777216);
    bf* xh   = (bf*)grab(16777216); bf* xl   = (bf*)grab(16777216);
    bf* W1eh = (bf*)grab(4194304);  bf* W1el = (bf*)grab(4194304);
    bf* W1rh = (bf*)grab(4194304);  bf* W1rl = (bf*)grab(4194304);
    bf* H1h[2] = {(bf*)grab(8388608), (bf*)grab(8388608)};
    bf* H1l[2] = {(bf*)grab(8388608), (bf*)grab(8388608)};
    bf* H2h[2] = {(bf*)grab(4194304), (bf*)grab(4194304)};
    bf* H2l[2] = {(bf*)grab(4194304), (bf*)grab(4194304)};
    bf* K1h = (bf*)grab(3145728);  bf* K1l = (bf*)grab(3145728);
    bf* K2h = (bf*)grab(1572864);  bf* K2l = (bf*)grab(1572864);

    cudaFuncSetAttribute(hgemm<0, 256>, cudaFuncAttributeMaxDynamicSharedMemorySize, smemBytes<256>());
    cudaFuncSetAttribute(hgemm<1, 256>, cudaFuncAttributeMaxDynamicSharedMemorySize, smemBytes<256>());
    cudaFuncSetAttribute(hgemm<2, 128>, cudaFuncAttributeMaxDynamicSharedMemorySize, smemBytes<128>());
    cudaFuncSetAttribute(hgemm<3, 64>,  cudaFuncAttributeMaxDynamicSharedMemorySize, smemBytes<64>());

    const int NOSPLIT = 0x40000000;

    // ---- launch 1: fused expands ----
    ExpandJobs E;
    E.W[0] = W1; E.out[0] = W1e;   E.J[0] = 128; E.I[0] = 256; E.rev[0] = 0; E.sgn[0] =  1.0f;
    E.W[1] = W1; E.out[1] = W1re;  E.J[1] = 256; E.I[1] = 128; E.rev[1] = 1; E.sgn[1] =  1.0f;
    E.W[2] = W2; E.out[2] = K1low; E.J[2] = 64;  E.I[2] = 128; E.rev[2] = 0; E.sgn[2] = -1.0f;
    E.W[3] = W2; E.out[3] = K2top; E.J[3] = 128; E.I[3] = 64;  E.rev[3] = 1; E.sgn[3] = -1.0f;
    E.start[0] = 0; E.start[1] = 8192; E.start[2] = 16384; E.start[3] = 18432; E.start[4] = 20480;
    expand_fused<<<20480, 256>>>(E);

    // ---- launch 2: fused packs ----
    PackJobs P;
    P.src[0] = x;     P.hi[0] = xh;                 P.lo[0] = xl;
    P.src[1] = W1e;   P.hi[1] = W1eh;               P.lo[1] = W1el;
    P.src[2] = W1re;  P.hi[2] = W1rh;               P.lo[2] = W1rl;
    P.src[3] = h1;    P.hi[3] = H1h[0];             P.lo[3] = H1l[0];
    P.src[4] = h2;    P.hi[4] = H2h[0];             P.lo[4] = H2l[0];
    P.src[5] = K1low; P.hi[5] = K1h + 1024 * 1024;  P.lo[5] = K1l + 1024 * 1024;
    P.src[6] = K2top; P.hi[6] = K2h;                P.lo[6] = K2l;
    P.start[0] = 0;     P.start[1] = 8192;  P.start[2] = 10240; P.start[3] = 12288;
    P.start[4] = 16384; P.start[5] = 18432; P.start[6] = 18944; P.start[7] = 19456;
    pack_fused<<<19456, 256>>>(P);

    // ---- launch 3: XR = x @ What1r  [4096,1024], K=2048 ----
    hgemm<0, 256><<<dim3(4, 32), 256, smemBytes<256>()>>>(
        xh, xl, 2048, nullptr, nullptr, 0, NOSPLIT,
        W1rh, W1rl, 1024, 2048, XR, 1024, nullptr, nullptr, nullptr, nullptr, nullptr, 0);
    // ---- launch 4: K1 top = What1@What1r + I  [1024,1024], K=2048 ----
    hgemm<3, 64><<<dim3(16, 8), 256, smemBytes<64>()>>>(
        W1eh, W1el, 2048, nullptr, nullptr, 0, NOSPLIT,
        W1rh, W1rl, 1024, 2048, nullptr, 1024, nullptr, nullptr, nullptr, K1h, K1l, 1);
    // ---- launch 5: K2 bottom = (-What2)@(-What2r)  [512,512], K=1024 ----
    hgemm<3, 64><<<dim3(8, 4), 256, smemBytes<64>()>>>(
        K1h + 1024 * 1024, K1l + 1024 * 1024, 1024, nullptr, nullptr, 0, NOSPLIT,
        K2h, K2l, 512, 1024, nullptr, 512, nullptr, nullptr, nullptr,
        K2h + 1024 * 512, K2l + 1024 * 512, 0);

    cudaMemcpyAsync(out, x, 33554432, cudaMemcpyDeviceToDevice, 0);
    float* out_h1 = out + 8388608;
    float* out_h2 = out + 12582912;

    // ---- launches 6..45: 20 iterations (launch 6 = GEMM1 iter0 -> ncu target)
    for (int it = 0; it < 20; ++it) {
        int rd = it & 1, wr = 1 - rd;
        bool last = (it == 19);
        float* c1 = last ? out_h1 : nullptr;
        float* c2 = last ? out_h2 : nullptr;
        bf* p1h = H1h[wr]; bf* p1l = H1l[wr];
        bf* p2h = last ? nullptr : H2h[wr];
        bf* p2l = last ? nullptr : H2l[wr];
        // H1' = H1 - a*clip([H1|H2]@K1 - XR)   [4096,1024], K=1536
        hgemm<1, 256><<<dim3(4, 32), 256, smemBytes<256>()>>>(
            H1h[rd], H1l[rd], 1024, H2h[rd], H2l[rd], 512, 1024,
            K1h, K1l, 1024, 1536, c1, 1024, XR, H1h[rd], H1l[rd], p1h, p1l, 0);
        // H2' = H2 - a*clip([H1'|H2]@K2)       [4096,512], K=1536
        hgemm<2, 128><<<dim3(4, 32), 256, smemBytes<128>()>>>(
            H1h[wr], H1l[wr], 1024, H2h[rd], H2l[rd], 512, 1024,
            K2h, K2l, 512, 1536, c2, 512, nullptr, H2h[rd], H2l[rd], p2h, p2l, 0);
    }
}